// round 8
// baseline (speedup 1.0000x reference)
#include <cuda_runtime.h>
#include <cstdint>

#define Bb 32
#define Nn 1024
#define Dd 512
#define Kk 64
#define KC 80            // K + G clusters
#define ROWS (Bb * Nn)   // 32768

// g_assign stored TRANSPOSED: [b][k][n]  (b*Kk + k)*Nn + n, tf32-pre-rounded
__device__ __align__(16) float g_assign[ROWS * Kk];
__device__ float g_asum_part[256 * Kk];
__device__ float g_ssq_part[Bb * 8];
// W pre-rounded + padded per chunk in the exact smem image [16][32][88]
__device__ __align__(16) float g_Wt[16 * 32 * 88];

// ---------------------------------------------------------------------------
__device__ __forceinline__ float to_tf32(float x) {
    uint32_t r;
    asm("cvt.rna.tf32.f32 %0, %1;" : "=r"(r) : "f"(x));
    return __uint_as_float(r);
}

__device__ __forceinline__ void mma8(float* d, const uint32_t* a,
                                     uint32_t b0, uint32_t b1) {
    asm volatile(
        "mma.sync.aligned.m16n8k8.row.col.f32.tf32.tf32.f32 "
        "{%0,%1,%2,%3}, {%4,%5,%6,%7}, {%8,%9}, {%0,%1,%2,%3};"
        : "+f"(d[0]), "+f"(d[1]), "+f"(d[2]), "+f"(d[3])
        : "r"(a[0]), "r"(a[1]), "r"(a[2]), "r"(a[3]), "r"(b0), "r"(b1));
}

__device__ __forceinline__ void cp16(void* sdst, const void* gsrc) {
    uint32_t s = (uint32_t)__cvta_generic_to_shared(sdst);
    asm volatile("cp.async.cg.shared.global [%0], [%1], 16;" :: "r"(s), "l"(gsrc));
}
__device__ __forceinline__ void cp_commit() {
    asm volatile("cp.async.commit_group;");
}
__device__ __forceinline__ void cp_wait0() {
    asm volatile("cp.async.wait_group 0;");
}

// ---------------------------------------------------------------------------
// prep: g_Wt[c][r][col] = tf32(W[(c*32+r)*80 + col]) for col<80, 0 pad to 88
// ---------------------------------------------------------------------------
__global__ void prep_wt(const float* __restrict__ W)
{
    int i = blockIdx.x * blockDim.x + threadIdx.x;
    if (i >= 16 * 32 * 88) return;
    int c   = i / 2816;
    int rem = i % 2816;
    int r   = rem / 88;
    int col = rem % 88;
    g_Wt[i] = (col < KC) ? to_tf32(W[(size_t)(c * 32 + r) * KC + col]) : 0.f;
}

// ---------------------------------------------------------------------------
// Kernel A: logits = x @ clusters ; BN ; softmax(80) ; keep 64 (transposed out)
// Block 128x80, 8 warps (4Mx2N), warp 32x40. All staging via cp.async
// (A raw f32 -> tf32 truncation inside MMA; B pre-rounded image).
// One cp group + one __syncthreads per chunk; copies overlap the MMA phase.
// Dynamic smem (floats): As[2][128][36]=9216, Bs[2][32][88]=5632  (59392 B)
// softmax overlay: Ls[128][81] @0, inv @10368, red @10496
// ---------------------------------------------------------------------------
#define ASSIGN_SMEM_BYTES 59392

__global__ __launch_bounds__(256, 2) void assign_kernel(
    const float* __restrict__ x,      // [32768, 512]
    const float* __restrict__ bnw, const float* __restrict__ bnb,
    const float* __restrict__ bnm, const float* __restrict__ bnv)
{
    extern __shared__ float dyn[];
    float* AsBase = dyn;                 // [2][128][36]
    float* BsBase = dyn + 9216;          // [2][32][88]
    float (*Ls)[81] = reinterpret_cast<float(*)[81]>(dyn);
    float* invp = dyn + 10368;
    float* redp = dyn + 10496;
    __shared__ float s_sc[KC], s_tc[KC];

    const int t = threadIdx.x;
    const int lane = t & 31;
    const int wid = t >> 5;
    const int warpM = wid & 3;
    const int warpN = wid >> 2;
    const int g   = lane >> 2;
    const int tig = lane & 3;
    const int row0 = blockIdx.x * 128;

    if (t < KC) {
        float iv = rsqrtf(bnv[t] + 1e-5f);
        float sc = bnw[t] * iv;
        s_sc[t] = sc;
        s_tc[t] = bnb[t] - bnm[t] * sc;
    }

    float acc[2][5][4];
#pragma unroll
    for (int a = 0; a < 2; a++)
#pragma unroll
        for (int b = 0; b < 5; b++)
#pragma unroll
            for (int c = 0; c < 4; c++) acc[a][b][c] = 0.f;

    // staging helper (pure cp.async): A rows i>>3, float4 col i&7
    const float* xrow = x + (size_t)row0 * Dd;

    // prologue: issue chunk 0
    {
#pragma unroll
        for (int j = 0; j < 4; j++) {
            int i = t + j * 256;
            int r = i >> 3, c4 = (i & 7) << 2;
            cp16(AsBase + r * 36 + c4, xrow + (size_t)r * Dd + c4);
        }
#pragma unroll
        for (int j = 0; j < 3; j++) {
            int i = t + j * 256;
            if (i < 704)
                cp16((char*)BsBase + i * 16, (const char*)g_Wt + i * 16);
        }
        cp_commit();
    }

    for (int c = 0; c < 16; c++) {
        const int p = c & 1;
        float* As = AsBase + p * (128 * 36);
        float* Bs = BsBase + p * (32 * 88);

        cp_wait0();          // chunk c resident
        __syncthreads();     // visibility + frees buffer 1-p

        // issue chunk c+1 into buffer 1-p (overlaps MMA phase below)
        if (c < 15) {
            const int kt = (c + 1) * 32;
            float* Ad = AsBase + (1 - p) * (128 * 36);
            char*  Bd = (char*)BsBase + (1 - p) * 11264;
            const char* Bsrc = (const char*)g_Wt + (size_t)(c + 1) * 11264;
#pragma unroll
            for (int j = 0; j < 4; j++) {
                int i = t + j * 256;
                int r = i >> 3, c4 = (i & 7) << 2;
                cp16(Ad + r * 36 + c4, xrow + (size_t)r * Dd + kt + c4);
            }
#pragma unroll
            for (int j = 0; j < 3; j++) {
                int i = t + j * 256;
                if (i < 704) cp16(Bd + i * 16, Bsrc + i * 16);
            }
            cp_commit();
        }

        // MMA phase
#pragma unroll
        for (int ks = 0; ks < 4; ks++) {
            const int kk = ks << 3;
            uint32_t af[2][4];
#pragma unroll
            for (int mf = 0; mf < 2; mf++) {
                const int rb = warpM * 32 + mf * 16 + g;
                af[mf][0] = __float_as_uint(As[(rb    ) * 36 + kk + tig    ]);
                af[mf][1] = __float_as_uint(As[(rb + 8) * 36 + kk + tig    ]);
                af[mf][2] = __float_as_uint(As[(rb    ) * 36 + kk + tig + 4]);
                af[mf][3] = __float_as_uint(As[(rb + 8) * 36 + kk + tig + 4]);
            }
#pragma unroll
            for (int nf = 0; nf < 5; nf++) {
                const int cb = warpN * 40 + nf * 8 + g;
                uint32_t b0 = __float_as_uint(Bs[(kk + tig    ) * 88 + cb]);
                uint32_t b1 = __float_as_uint(Bs[(kk + tig + 4) * 88 + cb]);
                mma8(acc[0][nf], af[0], b0, b1);
                mma8(acc[1][nf], af[1], b0, b1);
            }
        }
    }
    __syncthreads();   // buffers dead; softmax overlay begins

    // BN fold + stage logits
#pragma unroll
    for (int mf = 0; mf < 2; mf++)
#pragma unroll
        for (int nf = 0; nf < 5; nf++)
#pragma unroll
            for (int c = 0; c < 4; c++) {
                int row = warpM * 32 + mf * 16 + g + ((c >> 1) << 3);
                int col = warpN * 40 + nf * 8 + 2 * tig + (c & 1);
                Ls[row][col] = fmaf(acc[mf][nf][c], s_sc[col], s_tc[col]);
            }
    __syncthreads();

    if (t < 128) {
        float m = -1e30f;
#pragma unroll
        for (int j = 0; j < KC; j++) m = fmaxf(m, Ls[t][j]);
        float ssum = 0.f;
#pragma unroll
        for (int j = 0; j < KC; j++) {
            float e = __expf(Ls[t][j] - m);
            ssum += e;
            if (j < Kk) Ls[t][j] = e;
        }
        invp[t] = 1.f / ssum;
    }
    __syncthreads();

    // transposed, tf32-rounded store: g_assign[(b*64+k)*1024 + n]
    const int bidx = row0 >> 10;       // batch
    const int nbase = row0 & 1023;
#pragma unroll
    for (int i = t; i < 128 * Kk; i += 256) {
        int k = i >> 7, r = i & 127;
        float e = Ls[r][k] * invp[r];
        g_assign[((size_t)bidx * Kk + k) * Nn + nbase + r] = to_tf32(e);
    }

    // per-column partial sums (k fixed per thread in this mapping)
    float partial = 0.f;
#pragma unroll
    for (int i = t; i < 128 * Kk; i += 256) {
        int r = i >> 6, k = i & 63;
        partial += Ls[r][k] * invp[r];
    }
    redp[t] = partial;
    __syncthreads();
    if (t < 64)
        g_asum_part[blockIdx.x * Kk + t] =
            redp[t] + redp[t + 64] + redp[t + 128] + redp[t + 192];
}

// ---------------------------------------------------------------------------
// Kernel B: O[k][d] = sum_n aT[k,n]*x[n,d] - asum[k]*c2[d,k]   (round-7 exact)
// ---------------------------------------------------------------------------
__global__ __launch_bounds__(128, 4) void vlad_kernel(
    const float* __restrict__ x,     // [32768, 512]
    const float* __restrict__ c2,    // [512, 64]
    float* __restrict__ out)         // [32, 512*64]
{
    __shared__ float aT_s[2][64][36];
    __shared__ float x_s[2][32][72];
    __shared__ float asum_s[64];
    __shared__ float redsq[4];

    const int t = threadIdx.x;
    const int lane = t & 31;
    const int wid = t >> 5;
    const int warpM = wid & 1;
    const int warpN = wid >> 1;
    const int g   = lane >> 2;
    const int tig = lane & 3;
    const int b  = blockIdx.y;
    const int d0 = blockIdx.x * 64;

    if (t < 64) {
        float s = 0.f;
#pragma unroll
        for (int j = 0; j < 8; j++)
            s += g_asum_part[((b << 3) + j) * Kk + t];
        asum_s[t] = s;
    }

    float acc[2][4][4];
#pragma unroll
    for (int mf = 0; mf < 2; mf++)
#pragma unroll
        for (int nf = 0; nf < 4; nf++)
#pragma unroll
            for (int c = 0; c < 4; c++) acc[mf][nf][c] = 0.f;

    const float* xb  = x + (size_t)b * Nn * Dd + d0;
    const float* abT = g_assign + (size_t)b * Kk * Nn;

    const int xn = t >> 4, xq = (t & 15) << 2;
    float4 px[4];

#pragma unroll
    for (int j = 0; j < 4; j++) {
        int i = t + j * 128;
        int k = i >> 3, seg = i & 7;
        cp16(&aT_s[0][k][seg << 2], abT + (size_t)k * Nn + (seg << 2));
    }
    cp_commit();
#pragma unroll
    for (int j = 0; j < 4; j++)
        px[j] = *reinterpret_cast<const float4*>(&xb[(size_t)(xn + j * 8) * Dd + xq]);

    for (int c = 0; c < 32; c++) {
        const int p = c & 1;

        cp_wait0();
#pragma unroll
        for (int j = 0; j < 4; j++) {
            float* dst = &x_s[p][xn + j * 8][xq];
            dst[0] = to_tf32(px[j].x); dst[1] = to_tf32(px[j].y);
            dst[2] = to_tf32(px[j].z); dst[3] = to_tf32(px[j].w);
        }
        __syncthreads();

        if (c < 31) {
            const int n1 = (c + 1) * 32;
#pragma unroll
            for (int j = 0; j < 4; j++) {
                int i = t + j * 128;
                int k = i >> 3, seg = i & 7;
                cp16(&aT_s[1 - p][k][seg << 2],
                     abT + (size_t)k * Nn + n1 + (seg << 2));
            }
            cp_commit();
#pragma unroll
            for (int j = 0; j < 4; j++)
                px[j] = *reinterpret_cast<const float4*>(
                    &xb[(size_t)(n1 + xn + j * 8) * Dd + xq]);
        }

#pragma unroll
        for (int ks = 0; ks < 4; ks++) {
            const int kk = ks << 3;
            uint32_t af[2][4];
#pragma unroll
            for (int mf = 0; mf < 2; mf++) {
                const int rb = warpM * 32 + mf * 16 + g;
                af[mf][0] = __float_as_uint(aT_s[p][rb    ][kk + tig    ]);
                af[mf][1] = __float_as_uint(aT_s[p][rb + 8][kk + tig    ]);
                af[mf][2] = __float_as_uint(aT_s[p][rb    ][kk + tig + 4]);
                af[mf][3] = __float_as_uint(aT_s[p][rb + 8][kk + tig + 4]);
            }
#pragma unroll
            for (int nf = 0; nf < 4; nf++) {
                const int cb = warpN * 32 + nf * 8 + g;
                uint32_t b0 = __float_as_uint(x_s[p][kk + tig    ][cb]);
                uint32_t b1 = __float_as_uint(x_s[p][kk + tig + 4][cb]);
                mma8(acc[0][nf], af[0], b0, b1);
                mma8(acc[1][nf], af[1], b0, b1);
            }
        }
    }

    float* ob = out + (size_t)b * (Dd * Kk);
    float ssq = 0.f;
#pragma unroll
    for (int mf = 0; mf < 2; mf++)
#pragma unroll
        for (int nf = 0; nf < 4; nf++)
#pragma unroll
            for (int c = 0; c < 4; c++) {
                int k = warpM * 32 + mf * 16 + g + ((c >> 1) << 3);
                int d = d0 + warpN * 32 + nf * 8 + 2 * tig + (c & 1);
                float v = acc[mf][nf][c] - asum_s[k] * c2[(size_t)d * Kk + k];
                ob[(size_t)d * Kk + k] = v;
                ssq = fmaf(v, v, ssq);
            }
#pragma unroll
    for (int off = 16; off > 0; off >>= 1)
        ssq += __shfl_xor_sync(0xffffffffu, ssq, off);
    if (lane == 0) redsq[wid] = ssq;
    __syncthreads();
    if (t == 0)
        g_ssq_part[b * 8 + blockIdx.x] = redsq[0] + redsq[1] + redsq[2] + redsq[3];
}

// ---------------------------------------------------------------------------
// Kernel C: pure scale pass, 8 blocks per batch (256 blocks total)
// ---------------------------------------------------------------------------
__global__ __launch_bounds__(256) void norm_kernel(float* __restrict__ out)
{
    const int b     = blockIdx.x >> 3;
    const int slice = blockIdx.x & 7;
    const int t = threadIdx.x;

    float v = 0.f;
#pragma unroll
    for (int j = 0; j < 8; j++) v += g_ssq_part[b * 8 + j];
    float s1 = v + 1e-12f;
    float n1 = sqrtf(s1);
    float s2 = v / s1 + 1e-12f;
    const float sc = 1.f / (n1 * sqrtf(s2));

    float4* p = reinterpret_cast<float4*>(out + (size_t)b * (Dd * Kk)) +
                slice * 1024;
#pragma unroll
    for (int i = t; i < 1024; i += 256) {
        float4 w = p[i];
        w.x *= sc; w.y *= sc; w.z *= sc; w.w *= sc;
        p[i] = w;
    }
}

// ---------------------------------------------------------------------------
extern "C" void kernel_launch(void* const* d_in, const int* in_sizes, int n_in,
                              void* d_out, int out_size)
{
    const float* x   = (const float*)d_in[0];
    const float* W   = (const float*)d_in[1];
    const float* c2  = (const float*)d_in[2];
    const float* bnw = (const float*)d_in[3];
    const float* bnb = (const float*)d_in[4];
    const float* bnm = (const float*)d_in[5];
    const float* bnv = (const float*)d_in[6];
    float* out = (float*)d_out;

    cudaFuncSetAttribute(assign_kernel,
                         cudaFuncAttributeMaxDynamicSharedMemorySize,
                         ASSIGN_SMEM_BYTES);

    prep_wt<<<176, 256>>>(W);
    assign_kernel<<<ROWS / 128, 256, ASSIGN_SMEM_BYTES>>>(x, bnw, bnb, bnm, bnv);
    vlad_kernel<<<dim3(Dd / 64, Bb), 128>>>(x, c2, out);
    norm_kernel<<<Bb * 8, 256>>>(out);
}

// round 9
// speedup vs baseline: 1.2400x; 1.2400x over previous
#include <cuda_runtime.h>
#include <cstdint>

#define Bb 32
#define Nn 1024
#define Dd 512
#define Kk 64
#define KC 80            // K + G clusters
#define ROWS (Bb * Nn)   // 32768

// g_assign stored TRANSPOSED: [b][k][n]  (b*Kk + k)*Nn + n, tf32-pre-rounded
__device__ __align__(16) float g_assign[ROWS * Kk];
__device__ float g_asum_part[256 * Kk];
__device__ float g_ssq_part[Bb * 8];
// W transposed+rounded+padded per chunk, smem-exact image: [16][80][36]
__device__ __align__(16) float g_Wt[16 * 80 * 36];

// ---------------------------------------------------------------------------
__device__ __forceinline__ float to_tf32(float x) {
    uint32_t r;
    asm("cvt.rna.tf32.f32 %0, %1;" : "=r"(r) : "f"(x));
    return __uint_as_float(r);
}

__device__ __forceinline__ void mma8(float* d, const uint32_t* a,
                                     uint32_t b0, uint32_t b1) {
    asm volatile(
        "mma.sync.aligned.m16n8k8.row.col.f32.tf32.tf32.f32 "
        "{%0,%1,%2,%3}, {%4,%5,%6,%7}, {%8,%9}, {%0,%1,%2,%3};"
        : "+f"(d[0]), "+f"(d[1]), "+f"(d[2]), "+f"(d[3])
        : "r"(a[0]), "r"(a[1]), "r"(a[2]), "r"(a[3]), "r"(b0), "r"(b1));
}

__device__ __forceinline__ void ldsm4(uint32_t* r, uint32_t a) {
    asm volatile("ldmatrix.sync.aligned.m8n8.x4.shared.b16 {%0,%1,%2,%3}, [%4];"
        : "=r"(r[0]), "=r"(r[1]), "=r"(r[2]), "=r"(r[3]) : "r"(a));
}
__device__ __forceinline__ void ldsm2(uint32_t& r0, uint32_t& r1, uint32_t a) {
    asm volatile("ldmatrix.sync.aligned.m8n8.x2.shared.b16 {%0,%1}, [%2];"
        : "=r"(r0), "=r"(r1) : "r"(a));
}

__device__ __forceinline__ void cp16(void* sdst, const void* gsrc) {
    uint32_t s = (uint32_t)__cvta_generic_to_shared(sdst);
    asm volatile("cp.async.cg.shared.global [%0], [%1], 16;" :: "r"(s), "l"(gsrc));
}
__device__ __forceinline__ void cp_commit() { asm volatile("cp.async.commit_group;"); }
__device__ __forceinline__ void cp_wait0()  { asm volatile("cp.async.wait_group 0;"); }

__device__ __forceinline__ uint32_t s2u(const void* p) {
    return (uint32_t)__cvta_generic_to_shared(p);
}

// ---------------------------------------------------------------------------
// prep: g_Wt[c][n][kk] = tf32(W[(c*32+kk)*80 + n]) for kk<32, 0 pad to 36
// ---------------------------------------------------------------------------
__global__ void prep_wt(const float* __restrict__ W)
{
    int i = blockIdx.x * blockDim.x + threadIdx.x;
    if (i >= 16 * 80 * 36) return;
    int c   = i / 2880;
    int rem = i % 2880;
    int n   = rem / 36;
    int kk  = rem % 36;
    g_Wt[i] = (kk < 32) ? to_tf32(W[(size_t)(c * 32 + kk) * KC + n]) : 0.f;
}

// ---------------------------------------------------------------------------
// Kernel A: logits = x @ clusters ; BN ; softmax(80) ; keep 64 (transposed out)
// Block 128x80, 8 warps (4Mx2N), warp 32x40. Round-7 staging pipeline
// (double-buffered, reg prefetch, one barrier/chunk); fragment loads via
// ldmatrix (A: x4 per 16x8 frag, B: x2 per 8-col frag from transposed Bt).
// Dynamic smem (floats): As[2][128][36]=9216, Bt[2][80][36]=5760 (59904 B)
// softmax overlay: Ls[128][81] @0, inv @10368, red @10496
// ---------------------------------------------------------------------------
#define ASSIGN_SMEM_BYTES 59904

__global__ __launch_bounds__(256, 2) void assign_kernel(
    const float* __restrict__ x,      // [32768, 512]
    const float* __restrict__ bnw, const float* __restrict__ bnb,
    const float* __restrict__ bnm, const float* __restrict__ bnv)
{
    extern __shared__ float dyn[];
    float* AsBase = dyn;                 // [2][128*36]
    float* BtBase = dyn + 9216;          // [2][80*36]
    float (*Ls)[81] = reinterpret_cast<float(*)[81]>(dyn);
    float* invp = dyn + 10368;
    float* redp = dyn + 10496;
    __shared__ float s_sc[KC], s_tc[KC];

    const int t = threadIdx.x;
    const int lane = t & 31;
    const int wid = t >> 5;
    const int warpM = wid & 3;
    const int warpN = wid >> 2;
    const int row0 = blockIdx.x * 128;

    if (t < KC) {
        float iv = rsqrtf(bnv[t] + 1e-5f);
        float sc = bnw[t] * iv;
        s_sc[t] = sc;
        s_tc[t] = bnb[t] - bnm[t] * sc;
    }

    float acc[2][5][4];
#pragma unroll
    for (int a = 0; a < 2; a++)
#pragma unroll
        for (int b = 0; b < 5; b++)
#pragma unroll
            for (int c = 0; c < 4; c++) acc[a][b][c] = 0.f;

    // ldmatrix lane-address bases (byte offsets inside one buffer)
    const int q = lane >> 3;                 // A tile index 0..3
    const int lrow = lane & 7;
    uint32_t offAm[2];
#pragma unroll
    for (int mf = 0; mf < 2; mf++) {
        int rowA = warpM * 32 + mf * 16 + (q & 1) * 8 + lrow;
        int colA = (q >> 1) * 4;
        offAm[mf] = (uint32_t)((rowA * 36 + colA) * 4);
    }
    const int bl = lane & 15;
    uint32_t offBn[5];
#pragma unroll
    for (int nf = 0; nf < 5; nf++) {
        int rowB = warpN * 40 + nf * 8 + (bl & 7);
        int colB = (bl >> 3) * 4;
        offBn[nf] = (uint32_t)((rowB * 36 + colB) * 4);
    }
    const uint32_t uAs0 = s2u(AsBase);
    const uint32_t uBt0 = s2u(BtBase);

    float4 pa[4];
    float4 pb[3];
    const int ar = t >> 3, ac4 = (t & 7) << 2;

    // prologue: LDG chunk 0 (A from x, B from pre-built image)
#pragma unroll
    for (int j = 0; j < 4; j++)
        pa[j] = *reinterpret_cast<const float4*>(
            &x[(size_t)(row0 + ar + j * 32) * Dd + ac4]);
#pragma unroll
    for (int j = 0; j < 3; j++) {
        int i = t + j * 256;
        if (i < 720)
            pb[j] = *reinterpret_cast<const float4*>(g_Wt + i * 4);
    }

    for (int c = 0; c < 16; c++) {
        const int p = c & 1;
        float* As = AsBase + p * (128 * 36);
        float* Bt = BtBase + p * (80 * 36);

        // STS current chunk (A: tf32 round; B: verbatim image copy)
#pragma unroll
        for (int j = 0; j < 4; j++) {
            float* dst = As + (ar + j * 32) * 36 + ac4;
            dst[0] = to_tf32(pa[j].x); dst[1] = to_tf32(pa[j].y);
            dst[2] = to_tf32(pa[j].z); dst[3] = to_tf32(pa[j].w);
        }
#pragma unroll
        for (int j = 0; j < 3; j++) {
            int i = t + j * 256;
            if (i < 720)
                *reinterpret_cast<float4*>(Bt + i * 4) = pb[j];
        }
        __syncthreads();

        // LDG next chunk while MMAs run
        if (c < 15) {
            const int kt = (c + 1) * 32;
#pragma unroll
            for (int j = 0; j < 4; j++)
                pa[j] = *reinterpret_cast<const float4*>(
                    &x[(size_t)(row0 + ar + j * 32) * Dd + kt + ac4]);
            const float* wsrc = g_Wt + (size_t)(c + 1) * 2880;
#pragma unroll
            for (int j = 0; j < 3; j++) {
                int i = t + j * 256;
                if (i < 720)
                    pb[j] = *reinterpret_cast<const float4*>(wsrc + i * 4);
            }
        }

        // MMA phase (ldmatrix fragment loads)
        const uint32_t uAs = uAs0 + p * 18432;
        const uint32_t uBt = uBt0 + p * 11520;
#pragma unroll
        for (int ks = 0; ks < 4; ks++) {
            const uint32_t kb = (uint32_t)(ks * 32);   // 8 floats = 32 bytes
            uint32_t af[2][4];
            ldsm4(af[0], uAs + offAm[0] + kb);
            ldsm4(af[1], uAs + offAm[1] + kb);
            uint32_t b0[5], b1[5];
#pragma unroll
            for (int nf = 0; nf < 5; nf++)
                ldsm2(b0[nf], b1[nf], uBt + offBn[nf] + kb);
#pragma unroll
            for (int nf = 0; nf < 5; nf++) {
                mma8(acc[0][nf], af[0], b0[nf], b1[nf]);
                mma8(acc[1][nf], af[1], b0[nf], b1[nf]);
            }
        }
    }
    __syncthreads();   // buffers dead; softmax overlay begins

    // BN fold + stage logits
    const int g   = lane >> 2;
    const int tig = lane & 3;
#pragma unroll
    for (int mf = 0; mf < 2; mf++)
#pragma unroll
        for (int nf = 0; nf < 5; nf++)
#pragma unroll
            for (int c = 0; c < 4; c++) {
                int row = warpM * 32 + mf * 16 + g + ((c >> 1) << 3);
                int col = warpN * 40 + nf * 8 + 2 * tig + (c & 1);
                Ls[row][col] = fmaf(acc[mf][nf][c], s_sc[col], s_tc[col]);
            }
    __syncthreads();

    if (t < 128) {
        float m = -1e30f;
#pragma unroll
        for (int j = 0; j < KC; j++) m = fmaxf(m, Ls[t][j]);
        float ssum = 0.f;
#pragma unroll
        for (int j = 0; j < KC; j++) {
            float e = __expf(Ls[t][j] - m);
            ssum += e;
            if (j < Kk) Ls[t][j] = e;
        }
        invp[t] = 1.f / ssum;
    }
    __syncthreads();

    // transposed, tf32-rounded store: g_assign[(b*64+k)*1024 + n]
    const int bidx = row0 >> 10;       // batch
    const int nbase = row0 & 1023;
#pragma unroll
    for (int i = t; i < 128 * Kk; i += 256) {
        int k = i >> 7, r = i & 127;
        float e = Ls[r][k] * invp[r];
        g_assign[((size_t)bidx * Kk + k) * Nn + nbase + r] = to_tf32(e);
    }

    // per-column partial sums (k fixed per thread in this mapping)
    float partial = 0.f;
#pragma unroll
    for (int i = t; i < 128 * Kk; i += 256) {
        int r = i >> 6, k = i & 63;
        partial += Ls[r][k] * invp[r];
    }
    redp[t] = partial;
    __syncthreads();
    if (t < 64)
        g_asum_part[blockIdx.x * Kk + t] =
            redp[t] + redp[t + 64] + redp[t + 128] + redp[t + 192];
}

// ---------------------------------------------------------------------------
// Kernel B: O[k][d] = sum_n aT[k,n]*x[n,d] - asum[k]*c2[d,k]
// Round-7 pipeline; A-frag loads via ldmatrix.x4 (aT_s is [k][n], stride 36).
// ---------------------------------------------------------------------------
__global__ __launch_bounds__(128, 4) void vlad_kernel(
    const float* __restrict__ x,     // [32768, 512]
    const float* __restrict__ c2,    // [512, 64]
    float* __restrict__ out)         // [32, 512*64]
{
    __shared__ float aT_s[2][64][36];
    __shared__ float x_s[2][32][72];
    __shared__ float asum_s[64];
    __shared__ float redsq[4];

    const int t = threadIdx.x;
    const int lane = t & 31;
    const int wid = t >> 5;
    const int warpM = wid & 1;
    const int warpN = wid >> 1;
    const int g   = lane >> 2;
    const int tig = lane & 3;
    const int b  = blockIdx.y;
    const int d0 = blockIdx.x * 64;

    if (t < 64) {
        float s = 0.f;
#pragma unroll
        for (int j = 0; j < 8; j++)
            s += g_asum_part[((b << 3) + j) * Kk + t];
        asum_s[t] = s;
    }

    float acc[2][4][4];
#pragma unroll
    for (int mf = 0; mf < 2; mf++)
#pragma unroll
        for (int nf = 0; nf < 4; nf++)
#pragma unroll
            for (int c = 0; c < 4; c++) acc[mf][nf][c] = 0.f;

    // ldmatrix lane addresses for A (aT_s, stride 36 floats)
    const int q = lane >> 3;
    const int lrow = lane & 7;
    uint32_t offAm[2];
#pragma unroll
    for (int mf = 0; mf < 2; mf++) {
        int rowA = warpM * 32 + mf * 16 + (q & 1) * 8 + lrow;
        int colA = (q >> 1) * 4;
        offAm[mf] = (uint32_t)((rowA * 36 + colA) * 4);
    }
    const uint32_t uA0 = s2u(&aT_s[0][0][0]);

    const float* xb  = x + (size_t)b * Nn * Dd + d0;
    const float* abT = g_assign + (size_t)b * Kk * Nn;

    const int xn = t >> 4, xq = (t & 15) << 2;
    float4 px[4];

#pragma unroll
    for (int j = 0; j < 4; j++) {
        int i = t + j * 128;
        int k = i >> 3, seg = i & 7;
        cp16(&aT_s[0][k][seg << 2], abT + (size_t)k * Nn + (seg << 2));
    }
    cp_commit();
#pragma unroll
    for (int j = 0; j < 4; j++)
        px[j] = *reinterpret_cast<const float4*>(&xb[(size_t)(xn + j * 8) * Dd + xq]);

    for (int c = 0; c < 32; c++) {
        const int p = c & 1;

        cp_wait0();
#pragma unroll
        for (int j = 0; j < 4; j++) {
            float* dst = &x_s[p][xn + j * 8][xq];
            dst[0] = to_tf32(px[j].x); dst[1] = to_tf32(px[j].y);
            dst[2] = to_tf32(px[j].z); dst[3] = to_tf32(px[j].w);
        }
        __syncthreads();

        if (c < 31) {
            const int n1 = (c + 1) * 32;
#pragma unroll
            for (int j = 0; j < 4; j++) {
                int i = t + j * 128;
                int k = i >> 3, seg = i & 7;
                cp16(&aT_s[1 - p][k][seg << 2],
                     abT + (size_t)k * Nn + n1 + (seg << 2));
            }
            cp_commit();
#pragma unroll
            for (int j = 0; j < 4; j++)
                px[j] = *reinterpret_cast<const float4*>(
                    &xb[(size_t)(n1 + xn + j * 8) * Dd + xq]);
        }

        const uint32_t uA = uA0 + p * (64 * 36 * 4);
#pragma unroll
        for (int ks = 0; ks < 4; ks++) {
            const int kk = ks << 3;
            uint32_t af[2][4];
            ldsm4(af[0], uA + offAm[0] + (uint32_t)(ks * 32));
            ldsm4(af[1], uA + offAm[1] + (uint32_t)(ks * 32));
#pragma unroll
            for (int nf = 0; nf < 4; nf++) {
                const int cb = warpN * 32 + nf * 8 + g;
                uint32_t b0 = __float_as_uint(x_s[p][kk + tig    ][cb]);
                uint32_t b1 = __float_as_uint(x_s[p][kk + tig + 4][cb]);
                mma8(acc[0][nf], af[0], b0, b1);
                mma8(acc[1][nf], af[1], b0, b1);
            }
        }
    }

    float* ob = out + (size_t)b * (Dd * Kk);
    float ssq = 0.f;
#pragma unroll
    for (int mf = 0; mf < 2; mf++)
#pragma unroll
        for (int nf = 0; nf < 4; nf++)
#pragma unroll
            for (int c = 0; c < 4; c++) {
                int k = warpM * 32 + mf * 16 + g + ((c >> 1) << 3);
                int d = d0 + warpN * 32 + nf * 8 + 2 * tig + (c & 1);
                float v = acc[mf][nf][c] - asum_s[k] * c2[(size_t)d * Kk + k];
                ob[(size_t)d * Kk + k] = v;
                ssq = fmaf(v, v, ssq);
            }
#pragma unroll
    for (int off = 16; off > 0; off >>= 1)
        ssq += __shfl_xor_sync(0xffffffffu, ssq, off);
    if (lane == 0) redsq[wid] = ssq;
    __syncthreads();
    if (t == 0)
        g_ssq_part[b * 8 + blockIdx.x] = redsq[0] + redsq[1] + redsq[2] + redsq[3];
}

// ---------------------------------------------------------------------------
// Kernel C: pure scale pass, 32 blocks per batch (1024 blocks total).
// Each block redundantly computes the scale (bitwise identical) and scales
// its 1024-float slice (1 float4 per thread).
// ---------------------------------------------------------------------------
__global__ __launch_bounds__(256) void norm_kernel(float* __restrict__ out)
{
    const int b     = blockIdx.x >> 5;       // batch
    const int slice = blockIdx.x & 31;       // 0..31
    const int t = threadIdx.x;

    float v = 0.f;
#pragma unroll
    for (int j = 0; j < 8; j++) v += g_ssq_part[b * 8 + j];
    float s1 = v + 1e-12f;
    float n1 = sqrtf(s1);
    float s2 = v / s1 + 1e-12f;
    const float sc = 1.f / (n1 * sqrtf(s2));

    float4* p = reinterpret_cast<float4*>(out + (size_t)b * (Dd * Kk)) +
                slice * 256;
    float4 w = p[t];
    w.x *= sc; w.y *= sc; w.z *= sc; w.w *= sc;
    p[t] = w;
}

// ---------------------------------------------------------------------------
extern "C" void kernel_launch(void* const* d_in, const int* in_sizes, int n_in,
                              void* d_out, int out_size)
{
    const float* x   = (const float*)d_in[0];
    const float* W   = (const float*)d_in[1];
    const float* c2  = (const float*)d_in[2];
    const float* bnw = (const float*)d_in[3];
    const float* bnb = (const float*)d_in[4];
    const float* bnm = (const float*)d_in[5];
    const float* bnv = (const float*)d_in[6];
    float* out = (float*)d_out;

    cudaFuncSetAttribute(assign_kernel,
                         cudaFuncAttributeMaxDynamicSharedMemorySize,
                         ASSIGN_SMEM_BYTES);

    prep_wt<<<180, 256>>>(W);
    assign_kernel<<<ROWS / 128, 256, ASSIGN_SMEM_BYTES>>>(x, bnw, bnb, bnm, bnv);
    vlad_kernel<<<dim3(Dd / 64, Bb), 128>>>(x, c2, out);
    norm_kernel<<<Bb * 32, 256>>>(out);
}

// round 10
// speedup vs baseline: 1.8862x; 1.5211x over previous
#include <cuda_runtime.h>
#include <cuda_fp16.h>
#include <cstdint>

#define Bb 32
#define Nn 1024
#define Dd 512
#define Kk 64
#define KC 80            // K + G clusters
#define ROWS (Bb * Nn)   // 32768

// g_assign TRANSPOSED fp16: [b][k][n]  (b*Kk + k)*Nn + n
__device__ __align__(16) __half g_assign[ROWS * Kk];
__device__ float g_asum_part[256 * Kk];
__device__ float g_ssq_part[Bb * 8];
// W fp16 image per chunk: [16][80][40] halfs (rows n, cols k, pad 32->40)
__device__ __align__(16) __half g_Wh[16 * 80 * 40];

// ---------------------------------------------------------------------------
__device__ __forceinline__ void mma16(float* d, const uint32_t* a,
                                      uint32_t b0, uint32_t b1) {
    asm volatile(
        "mma.sync.aligned.m16n8k16.row.col.f32.f16.f16.f32 "
        "{%0,%1,%2,%3}, {%4,%5,%6,%7}, {%8,%9}, {%0,%1,%2,%3};"
        : "+f"(d[0]), "+f"(d[1]), "+f"(d[2]), "+f"(d[3])
        : "r"(a[0]), "r"(a[1]), "r"(a[2]), "r"(a[3]), "r"(b0), "r"(b1));
}

__device__ __forceinline__ void ldsm4(uint32_t* r, uint32_t a) {
    asm volatile("ldmatrix.sync.aligned.m8n8.x4.shared.b16 {%0,%1,%2,%3}, [%4];"
        : "=r"(r[0]), "=r"(r[1]), "=r"(r[2]), "=r"(r[3]) : "r"(a));
}
__device__ __forceinline__ void ldsm2(uint32_t& r0, uint32_t& r1, uint32_t a) {
    asm volatile("ldmatrix.sync.aligned.m8n8.x2.shared.b16 {%0,%1}, [%2];"
        : "=r"(r0), "=r"(r1) : "r"(a));
}
__device__ __forceinline__ void ldsm2t(uint32_t& r0, uint32_t& r1, uint32_t a) {
    asm volatile("ldmatrix.sync.aligned.m8n8.x2.trans.shared.b16 {%0,%1}, [%2];"
        : "=r"(r0), "=r"(r1) : "r"(a));
}

__device__ __forceinline__ void cp16(void* sdst, const void* gsrc) {
    uint32_t s = (uint32_t)__cvta_generic_to_shared(sdst);
    asm volatile("cp.async.cg.shared.global [%0], [%1], 16;" :: "r"(s), "l"(gsrc));
}
__device__ __forceinline__ void cp_commit() { asm volatile("cp.async.commit_group;"); }
__device__ __forceinline__ void cp_wait0()  { asm volatile("cp.async.wait_group 0;"); }

__device__ __forceinline__ uint32_t s2u(const void* p) {
    return (uint32_t)__cvta_generic_to_shared(p);
}

// ---------------------------------------------------------------------------
// prep: g_Wh[c][n][kk] = half(W[(c*32+kk)*80 + n]) for kk<32, 0 pad to 40
// ---------------------------------------------------------------------------
__global__ void prep_wh(const float* __restrict__ W)
{
    int i = blockIdx.x * blockDim.x + threadIdx.x;
    if (i >= 16 * 80 * 40) return;
    int c   = i / 3200;
    int rem = i % 3200;
    int n   = rem / 40;
    int kk  = rem % 40;
    g_Wh[i] = (kk < 32) ? __float2half_rn(W[(size_t)(c * 32 + kk) * KC + n])
                        : __half(0.f);
}

// ---------------------------------------------------------------------------
// Kernel A: logits = x @ clusters ; BN ; softmax(80) ; keep 64 (fp16 out,
// transposed). Block 128x80, 8 warps (4Mx2N), warp 32x40, fp16 m16n8k16.
// Dynamic smem bytes: As[2][128][40]h @0 (20480), Bt[2][80][40]h @20480
// (12800) -> 33280.  Softmax overlay: Ls f32[128][81] @0, inv @41472B,
// red @41984B -> 43008 total.
// ---------------------------------------------------------------------------
#define ASSIGN_SMEM_BYTES 43008

__global__ __launch_bounds__(256, 2) void assign_kernel(
    const float* __restrict__ x,      // [32768, 512]
    const float* __restrict__ bnw, const float* __restrict__ bnb,
    const float* __restrict__ bnm, const float* __restrict__ bnv)
{
    extern __shared__ float dynf[];
    __half* AsBase = reinterpret_cast<__half*>(dynf);            // [2][128*40]
    __half* BtBase = reinterpret_cast<__half*>(dynf + 5120);     // [2][80*40]
    float (*Ls)[81] = reinterpret_cast<float(*)[81]>(dynf);
    float* invp = dynf + 10368;
    float* redp = dynf + 10496;
    __shared__ float s_sc[KC], s_tc[KC];

    const int t = threadIdx.x;
    const int lane = t & 31;
    const int wid = t >> 5;
    const int warpM = wid & 3;
    const int warpN = wid >> 2;
    const int row0 = blockIdx.x * 128;

    if (t < KC) {
        float iv = rsqrtf(bnv[t] + 1e-5f);
        float sc = bnw[t] * iv;
        s_sc[t] = sc;
        s_tc[t] = bnb[t] - bnm[t] * sc;
    }

    float acc[2][5][4];
#pragma unroll
    for (int a = 0; a < 2; a++)
#pragma unroll
        for (int b = 0; b < 5; b++)
#pragma unroll
            for (int c = 0; c < 4; c++) acc[a][b][c] = 0.f;

    // ldmatrix byte-offset bases within one buffer
    const int q = lane >> 3;
    const int lrow = lane & 7;
    uint32_t offA[2];
#pragma unroll
    for (int mf = 0; mf < 2; mf++)
        offA[mf] = (uint32_t)((warpM * 32 + mf * 16 + (q & 1) * 8 + lrow) * 80
                              + (q >> 1) * 16);
    const int bl = lane & 15;
    uint32_t offB[5];
#pragma unroll
    for (int nf = 0; nf < 5; nf++)
        offB[nf] = (uint32_t)((warpN * 40 + nf * 8 + (bl & 7)) * 80
                              + (bl >> 3) * 16);
    const uint32_t uAs0 = s2u(AsBase);
    const uint32_t uBt0 = s2u(BtBase);

    float4 pa[4];
    uint4  pb[2];
    const int ar = t >> 3, ac4 = (t & 7) << 2;

    // prologue: LDG chunk 0 (A from x f32; B from fp16 image)
#pragma unroll
    for (int j = 0; j < 4; j++)
        pa[j] = *reinterpret_cast<const float4*>(
            &x[(size_t)(row0 + ar + j * 32) * Dd + ac4]);
    pb[0] = *reinterpret_cast<const uint4*>((const char*)g_Wh + t * 16);
    if (t < 144)
        pb[1] = *reinterpret_cast<const uint4*>((const char*)g_Wh + (t + 256) * 16);

    for (int c = 0; c < 16; c++) {
        const int p = c & 1;
        __half* As = AsBase + p * (128 * 40);
        __half* Bt = BtBase + p * (80 * 40);

        // STS current chunk (A: f32->h2 pack; B: verbatim)
#pragma unroll
        for (int j = 0; j < 4; j++) {
            int i = t + j * 256;
            int r = i >> 3, c4 = (i & 7) << 2;
            __half2 h01 = __floats2half2_rn(pa[j].x, pa[j].y);
            __half2 h23 = __floats2half2_rn(pa[j].z, pa[j].w);
            __half2* dst = reinterpret_cast<__half2*>(As + r * 40 + c4);
            dst[0] = h01; dst[1] = h23;
        }
        *reinterpret_cast<uint4*>((char*)Bt + t * 16) = pb[0];
        if (t < 144)
            *reinterpret_cast<uint4*>((char*)Bt + (t + 256) * 16) = pb[1];
        __syncthreads();

        // LDG next chunk while MMAs run
        if (c < 15) {
            const int kt = (c + 1) * 32;
#pragma unroll
            for (int j = 0; j < 4; j++)
                pa[j] = *reinterpret_cast<const float4*>(
                    &x[(size_t)(row0 + ar + j * 32) * Dd + kt + ac4]);
            const char* ws = (const char*)g_Wh + (size_t)(c + 1) * 6400;
            pb[0] = *reinterpret_cast<const uint4*>(ws + t * 16);
            if (t < 144)
                pb[1] = *reinterpret_cast<const uint4*>(ws + (t + 256) * 16);
        }

        // MMA phase: 2 k16-steps
        const uint32_t uAs = uAs0 + p * 10240;
        const uint32_t uBt = uBt0 + p * 6400;
#pragma unroll
        for (int ks = 0; ks < 2; ks++) {
            const uint32_t kb = (uint32_t)(ks * 32);   // 16 halfs = 32 bytes
            uint32_t af[2][4];
            ldsm4(af[0], uAs + offA[0] + kb);
            ldsm4(af[1], uAs + offA[1] + kb);
            uint32_t b0[5], b1[5];
#pragma unroll
            for (int nf = 0; nf < 5; nf++)
                ldsm2(b0[nf], b1[nf], uBt + offB[nf] + kb);
#pragma unroll
            for (int nf = 0; nf < 5; nf++) {
                mma16(acc[0][nf], af[0], b0[nf], b1[nf]);
                mma16(acc[1][nf], af[1], b0[nf], b1[nf]);
            }
        }
    }
    __syncthreads();   // buffers dead; softmax overlay begins

    // BN fold + stage logits
    const int g   = lane >> 2;
    const int tig = lane & 3;
#pragma unroll
    for (int mf = 0; mf < 2; mf++)
#pragma unroll
        for (int nf = 0; nf < 5; nf++)
#pragma unroll
            for (int c = 0; c < 4; c++) {
                int row = warpM * 32 + mf * 16 + g + ((c >> 1) << 3);
                int col = warpN * 40 + nf * 8 + 2 * tig + (c & 1);
                Ls[row][col] = fmaf(acc[mf][nf][c], s_sc[col], s_tc[col]);
            }
    __syncthreads();

    if (t < 128) {
        float m = -1e30f;
#pragma unroll
        for (int j = 0; j < KC; j++) m = fmaxf(m, Ls[t][j]);
        float ssum = 0.f;
#pragma unroll
        for (int j = 0; j < KC; j++) {
            float e = __expf(Ls[t][j] - m);
            ssum += e;
            if (j < Kk) Ls[t][j] = e;
        }
        invp[t] = 1.f / ssum;
    }
    __syncthreads();

    // transposed fp16 store: g_assign[(b*64+k)*1024 + n]
    const int bidx = row0 >> 10;
    const int nbase = row0 & 1023;
#pragma unroll
    for (int i = t; i < 128 * Kk; i += 256) {
        int k = i >> 7, r = i & 127;
        float e = Ls[r][k] * invp[r];
        g_assign[((size_t)bidx * Kk + k) * Nn + nbase + r] = __float2half_rn(e);
    }

    // per-column partial sums (f32, k fixed per thread)
    float partial = 0.f;
#pragma unroll
    for (int i = t; i < 128 * Kk; i += 256) {
        int r = i >> 6, k = i & 63;
        partial += Ls[r][k] * invp[r];
    }
    redp[t] = partial;
    __syncthreads();
    if (t < 64)
        g_asum_part[blockIdx.x * Kk + t] =
            redp[t] + redp[t + 64] + redp[t + 128] + redp[t + 192];
}

// ---------------------------------------------------------------------------
// Kernel B: O[k][d] = sum_n aT[k,n]*x[n,d] - asum[k]*c2[d,k]   (fp16 MMA)
// 128 threads, 4 warps (2Mk x 2Nd), warp 32x32.
// aT: cp.async fp16 verbatim; x: LDG f32 -> h2 pack STS.
// A frags: ldsm4; B frags: ldsm2.trans on x_s[n][d].
// ---------------------------------------------------------------------------
__global__ __launch_bounds__(128, 4) void vlad_kernel(
    const float* __restrict__ x,     // [32768, 512]
    const float* __restrict__ c2,    // [512, 64]
    float* __restrict__ out)         // [32, 512*64]
{
    __shared__ __half aT_s[2][64][40];   // stride 80B
    __shared__ __half x_s[2][32][72];    // stride 144B
    __shared__ float asum_s[64];
    __shared__ float redsq[4];

    const int t = threadIdx.x;
    const int lane = t & 31;
    const int wid = t >> 5;
    const int warpM = wid & 1;
    const int warpN = wid >> 1;
    const int g   = lane >> 2;
    const int tig = lane & 3;
    const int b  = blockIdx.y;
    const int d0 = blockIdx.x * 64;

    if (t < 64) {
        float s = 0.f;
#pragma unroll
        for (int j = 0; j < 8; j++)
            s += g_asum_part[((b << 3) + j) * Kk + t];
        asum_s[t] = s;
    }

    float acc[2][4][4];
#pragma unroll
    for (int mf = 0; mf < 2; mf++)
#pragma unroll
        for (int nf = 0; nf < 4; nf++)
#pragma unroll
            for (int c = 0; c < 4; c++) acc[mf][nf][c] = 0.f;

    // ldmatrix byte-offset bases
    const int q = lane >> 3;
    const int lrow = lane & 7;
    uint32_t offA[2];
#pragma unroll
    for (int mf = 0; mf < 2; mf++)
        offA[mf] = (uint32_t)((warpM * 32 + mf * 16 + (q & 1) * 8 + lrow) * 80
                              + (q >> 1) * 16);
    const int bl = lane & 15;
    uint32_t offX[4];
#pragma unroll
    for (int nf = 0; nf < 4; nf++)
        offX[nf] = (uint32_t)(bl * 144 + (warpN * 32 + nf * 8) * 2);
    const uint32_t uA0 = s2u(&aT_s[0][0][0]);
    const uint32_t uX0 = s2u(&x_s[0][0][0]);

    const float*  xb  = x + (size_t)b * Nn * Dd + d0;
    const __half* abT = g_assign + (size_t)b * Kk * Nn;

    const int xn = t >> 4, xq = (t & 15) << 2;
    float4 px[4];

    // prologue: a(0) via cp.async (2 cp16/thread); x(0) via LDG
#pragma unroll
    for (int j = 0; j < 2; j++) {
        int i = t + j * 128;               // 256 x 16B segs: k=i>>2, seg=i&3
        int k = i >> 2, seg = i & 3;
        cp16(&aT_s[0][k][seg << 3], abT + (size_t)k * Nn + (seg << 3));
    }
    cp_commit();
#pragma unroll
    for (int j = 0; j < 4; j++)
        px[j] = *reinterpret_cast<const float4*>(&xb[(size_t)(xn + j * 8) * Dd + xq]);

    for (int c = 0; c < 32; c++) {
        const int p = c & 1;

        cp_wait0();
#pragma unroll
        for (int j = 0; j < 4; j++) {
            __half2 h01 = __floats2half2_rn(px[j].x, px[j].y);
            __half2 h23 = __floats2half2_rn(px[j].z, px[j].w);
            __half2* dst = reinterpret_cast<__half2*>(&x_s[p][xn + j * 8][xq]);
            dst[0] = h01; dst[1] = h23;
        }
        __syncthreads();

        if (c < 31) {
            const int n1 = (c + 1) * 32;
#pragma unroll
            for (int j = 0; j < 2; j++) {
                int i = t + j * 128;
                int k = i >> 2, seg = i & 3;
                cp16(&aT_s[1 - p][k][seg << 3],
                     abT + (size_t)k * Nn + n1 + (seg << 3));
            }
            cp_commit();
#pragma unroll
            for (int j = 0; j < 4; j++)
                px[j] = *reinterpret_cast<const float4*>(
                    &xb[(size_t)(n1 + xn + j * 8) * Dd + xq]);
        }

        const uint32_t uA = uA0 + p * 5120;
        const uint32_t uX = uX0 + p * 4608;
#pragma unroll
        for (int ks = 0; ks < 2; ks++) {
            uint32_t af[2][4];
            ldsm4(af[0], uA + offA[0] + ks * 32);
            ldsm4(af[1], uA + offA[1] + ks * 32);
            uint32_t b0[4], b1[4];
#pragma unroll
            for (int nf = 0; nf < 4; nf++)
                ldsm2t(b0[nf], b1[nf], uX + offX[nf] + ks * 2304);
#pragma unroll
            for (int nf = 0; nf < 4; nf++) {
                mma16(acc[0][nf], af[0], b0[nf], b1[nf]);
                mma16(acc[1][nf], af[1], b0[nf], b1[nf]);
            }
        }
    }

    // epilogue: rank-1 correction + store + sumsq partial
    float* ob = out + (size_t)b * (Dd * Kk);
    float ssq = 0.f;
#pragma unroll
    for (int mf = 0; mf < 2; mf++)
#pragma unroll
        for (int nf = 0; nf < 4; nf++)
#pragma unroll
            for (int c = 0; c < 4; c++) {
                int k = warpM * 32 + mf * 16 + g + ((c >> 1) << 3);
                int d = d0 + warpN * 32 + nf * 8 + 2 * tig + (c & 1);
                float v = acc[mf][nf][c] - asum_s[k] * c2[(size_t)d * Kk + k];
                ob[(size_t)d * Kk + k] = v;
                ssq = fmaf(v, v, ssq);
            }
#pragma unroll
    for (int off = 16; off > 0; off >>= 1)
        ssq += __shfl_xor_sync(0xffffffffu, ssq, off);
    if (lane == 0) redsq[wid] = ssq;
    __syncthreads();
    if (t == 0)
        g_ssq_part[b * 8 + blockIdx.x] = redsq[0] + redsq[1] + redsq[2] + redsq[3];
}

// ---------------------------------------------------------------------------
// Kernel C: pure scale pass, 32 blocks per batch (1024 blocks total)
// ---------------------------------------------------------------------------
__global__ __launch_bounds__(256) void norm_kernel(float* __restrict__ out)
{
    const int b     = blockIdx.x >> 5;
    const int slice = blockIdx.x & 31;
    const int t = threadIdx.x;

    float v = 0.f;
#pragma unroll
    for (int j = 0; j < 8; j++) v += g_ssq_part[b * 8 + j];
    float s1 = v + 1e-12f;
    float n1 = sqrtf(s1);
    float s2 = v / s1 + 1e-12f;
    const float sc = 1.f / (n1 * sqrtf(s2));

    float4* p = reinterpret_cast<float4*>(out + (size_t)b * (Dd * Kk)) +
                slice * 256;
    float4 w = p[t];
    w.x *= sc; w.y *= sc; w.z *= sc; w.w *= sc;
    p[t] = w;
}

// ---------------------------------------------------------------------------
extern "C" void kernel_launch(void* const* d_in, const int* in_sizes, int n_in,
                              void* d_out, int out_size)
{
    const float* x   = (const float*)d_in[0];
    const float* W   = (const float*)d_in[1];
    const float* c2  = (const float*)d_in[2];
    const float* bnw = (const float*)d_in[3];
    const float* bnb = (const float*)d_in[4];
    const float* bnm = (const float*)d_in[5];
    const float* bnv = (const float*)d_in[6];
    float* out = (float*)d_out;

    cudaFuncSetAttribute(assign_kernel,
                         cudaFuncAttributeMaxDynamicSharedMemorySize,
                         ASSIGN_SMEM_BYTES);

    prep_wh<<<200, 256>>>(W);
    assign_kernel<<<ROWS / 128, 256, ASSIGN_SMEM_BYTES>>>(x, bnw, bnb, bnm, bnv);
    vlad_kernel<<<dim3(Dd / 64, Bb), 128>>>(x, c2, out);
    norm_kernel<<<Bb * 32, 256>>>(out);
}